// round 8
// baseline (speedup 1.0000x reference)
#include <cuda_runtime.h>
#include <cuda_bf16.h>
#include <math.h>
#include <stdint.h>

#define BB 8
#define TT 1024
#define VV 2048

// Scratch (__device__ globals: allocation-free rule)
__device__ __nv_bfloat16 g_Ebf[TT];            // bf16-rounded exp(vw[d])
__device__ float         g_Sinv[TT];           // 1 / prefix_sum(round_bf16(exp(vw)))
__device__ __nv_bfloat16 g_Mhi[BB][TT][TT];    // hi = bf16(M)            (16MB)
__device__ __nv_bfloat16 g_Mlo[BB][TT][TT];    // lo = bf16(M - hi)       (16MB)
__device__ __nv_bfloat16 g_a2h[BB][TT][TT];    // pre-softmax scores, bf16 (16MB)

// ---------------------------------------------------------------------------
// Kernel 1: E, Sinv.  Round E to bf16 FIRST, then scan the rounded values so
// the layer-1 softmax weights used by the GEMM sum to ~1 exactly.
// ---------------------------------------------------------------------------
__global__ void k_prefix(const float* __restrict__ vw) {
    __shared__ float sc[TT];
    int i = threadIdx.x;                  // blockDim = 1024
    float e = expf(vw[i]);
    __nv_bfloat16 eb = __float2bfloat16(e);
    float er = __bfloat162float(eb);
    g_Ebf[i] = eb;
    sc[i] = er;
    __syncthreads();
    for (int off = 1; off < TT; off <<= 1) {
        float v = (i >= off) ? sc[i - off] : 0.0f;
        __syncthreads();
        sc[i] += v;
        __syncthreads();
    }
    g_Sinv[i] = 1.0f / sc[i];
}

// ---------------------------------------------------------------------------
// Kernel 2: gather M[b][t][s'] = W[idx[b,t]][idx[b,s']] -> split bf16 hi/lo
// ---------------------------------------------------------------------------
__global__ __launch_bounds__(256) void k_gather(const int* __restrict__ idx,
                                                const float* __restrict__ W) {
    int t = blockIdx.x;
    int b = blockIdx.y;
    __shared__ float row[VV];
    __shared__ int   sidx[TT];

    int wr = idx[b * TT + t];
    const float4* src = (const float4*)(W + (size_t)wr * VV);
    float4* rdst = (float4*)row;
    for (int i = threadIdx.x; i < VV / 4; i += 256) rdst[i] = src[i];
    const int4* isrc = (const int4*)(idx + b * TT);
    int4* idst = (int4*)sidx;
    for (int i = threadIdx.x; i < TT / 4; i += 256) idst[i] = isrc[i];
    __syncthreads();

    __nv_bfloat162* ohi = (__nv_bfloat162*)(&g_Mhi[b][t][0]);
    __nv_bfloat162* olo = (__nv_bfloat162*)(&g_Mlo[b][t][0]);
    for (int p = threadIdx.x; p < TT / 2; p += 256) {
        float v0 = row[sidx[2 * p + 0]];
        float v1 = row[sidx[2 * p + 1]];
        __nv_bfloat16 h0 = __float2bfloat16(v0);
        __nv_bfloat16 h1 = __float2bfloat16(v1);
        float l0 = v0 - __bfloat162float(h0);   // exact in fp32
        float l1 = v1 - __bfloat162float(h1);
        __nv_bfloat162 hp; hp.x = h0; hp.y = h1;
        ohi[p] = hp;
        olo[p] = __floats2bfloat162_rn(l0, l1);
    }
}

// ---------------------------------------------------------------------------
// Kernel 3: split-bf16 tensor-core GEMM, 2-stage cp.async pipeline.
//   a2[b][t][s] = Sinv[s] * sum_{k<=s} (hi[t,k]+lo[t,k]) * E[s-k]   -> bf16
// ---------------------------------------------------------------------------
#define APITCH 24            // bf16 units per A row in smem (48B, conflict-free)

__device__ __forceinline__ uint32_t smem_u32(const void* p) {
    return (uint32_t)__cvta_generic_to_shared(p);
}
__device__ __forceinline__ void cp16(uint32_t dst, const void* src) {
    asm volatile("cp.async.ca.shared.global [%0], [%1], 16;\n" :: "r"(dst), "l"(src));
}

__global__ __launch_bounds__(256, 2) void k_gemm() {
    int b = blockIdx.y;
    int p = blockIdx.x;
    int ti = 0;
    while ((ti + 1) * (ti + 2) / 2 <= p) ti++;
    int si = p - ti * (ti + 1) / 2;
    int t0 = ti * 128;
    int s0 = si * 128;

    __shared__ __align__(16) __nv_bfloat16 As[2][2][128 * APITCH]; // [stage][plane] 24 KB
    __shared__ __align__(16) unsigned char Bs[2][16 * 256];        // [stage] 8 KB swizzled
    __shared__ __nv_bfloat16 sE[TT];                               // 2 KB
    __shared__ float sSinv[128];

    int tid  = threadIdx.x;
    int wid  = tid >> 5;
    int lane = tid & 31;
    int m_base = (wid >> 1) * 32;
    int n_base = (wid & 1) * 64;

    {
        const uint2* esrc = (const uint2*)g_Ebf;
        uint2* edst = (uint2*)sE;
        for (int i = tid; i < TT / 4; i += 256) edst[i] = esrc[i];
        if (tid < 128) sSinv[tid] = g_Sinv[s0 + tid];
    }

    float acc[2][8][4];
#pragma unroll
    for (int mi = 0; mi < 2; mi++)
#pragma unroll
        for (int nj = 0; nj < 8; nj++)
#pragma unroll
            for (int r = 0; r < 4; r++) acc[mi][nj][r] = 0.0f;

    int a_row = tid >> 1;
    int a_vec = tid & 1;
    int b_k  = tid >> 4;
    int b_vn = tid & 15;
    int nsteps = (s0 + 128) >> 4;

    auto issueA = [&](int stage, int k0) {
        uint32_t d0 = smem_u32(&As[stage][0][a_row * APITCH + a_vec * 8]);
        uint32_t d1 = smem_u32(&As[stage][1][a_row * APITCH + a_vec * 8]);
        cp16(d0, &g_Mhi[b][t0 + a_row][k0 + a_vec * 8]);
        cp16(d1, &g_Mlo[b][t0 + a_row][k0 + a_vec * 8]);
        asm volatile("cp.async.commit_group;\n");
    };
    auto issueB = [&](int stage, int k0) {
        union { __nv_bfloat16 h[8]; uint4 u; } pk;
        int dbase = (s0 + b_vn * 8) - (k0 + b_k);
#pragma unroll
        for (int j = 0; j < 8; j++) {
            int d = dbase + j;
            pk.h[j] = (d >= 0) ? sE[d] : __float2bfloat16(0.0f);
        }
        int phys = b_k * 256 + ((b_vn ^ (b_k & 7)) * 16);
        *(uint4*)(Bs[stage] + phys) = pk.u;
    };

    __syncthreads();   // sE/sSinv ready (needed by issueB)
    issueA(0, 0);
    issueB(0, 0);

    for (int step = 0; step < nsteps; step++) {
        int stage = step & 1;
        asm volatile("cp.async.wait_group 0;\n");
        __syncthreads();

        if (step + 1 < nsteps) {
            issueA(stage ^ 1, (step + 1) * 16);
            issueB(stage ^ 1, (step + 1) * 16);
        }

        uint32_t bfr[8][2];
#pragma unroll
        for (int nj2 = 0; nj2 < 4; nj2++) {
            int nvec = (n_base >> 3) + nj2 * 2 + (lane >> 4);
            int krow = lane & 15;
            uint32_t addr = smem_u32(Bs[stage] + krow * 256 + ((nvec ^ (krow & 7)) * 16));
            uint32_t r0, r1, r2, r3;
            asm volatile("ldmatrix.sync.aligned.m8n8.x4.trans.shared.b16 {%0,%1,%2,%3}, [%4];"
                         : "=r"(r0), "=r"(r1), "=r"(r2), "=r"(r3)
                         : "r"(addr));
            bfr[nj2 * 2 + 0][0] = r0; bfr[nj2 * 2 + 0][1] = r1;
            bfr[nj2 * 2 + 1][0] = r2; bfr[nj2 * 2 + 1][1] = r3;
        }

#pragma unroll
        for (int plane = 0; plane < 2; plane++) {
            uint32_t afr[2][4];
#pragma unroll
            for (int mi = 0; mi < 2; mi++) {
                int row = m_base + mi * 16 + (lane & 15);
                uint32_t addr = smem_u32(&As[stage][plane][row * APITCH + (lane >> 4) * 8]);
                asm volatile("ldmatrix.sync.aligned.m8n8.x4.shared.b16 {%0,%1,%2,%3}, [%4];"
                             : "=r"(afr[mi][0]), "=r"(afr[mi][1]),
                               "=r"(afr[mi][2]), "=r"(afr[mi][3])
                             : "r"(addr));
            }
#pragma unroll
            for (int mi = 0; mi < 2; mi++)
#pragma unroll
                for (int nj = 0; nj < 8; nj++) {
                    asm volatile(
                        "mma.sync.aligned.m16n8k16.row.col.f32.bf16.bf16.f32 "
                        "{%0,%1,%2,%3}, {%4,%5,%6,%7}, {%8,%9}, {%0,%1,%2,%3};"
                        : "+f"(acc[mi][nj][0]), "+f"(acc[mi][nj][1]),
                          "+f"(acc[mi][nj][2]), "+f"(acc[mi][nj][3])
                        : "r"(afr[mi][0]), "r"(afr[mi][1]), "r"(afr[mi][2]), "r"(afr[mi][3]),
                          "r"(bfr[nj][0]), "r"(bfr[nj][1]));
                }
        }
    }

    // ---- epilogue: scale by Sinv[s], store bf16 ----
    // m16n8k16 D-fragment: c0,c1 -> (row, col/col+1); c2,c3 -> (row+8, col/col+1)
#pragma unroll
    for (int mi = 0; mi < 2; mi++) {
#pragma unroll
        for (int nj = 0; nj < 8; nj++) {
            int row0 = m_base + mi * 16 + (lane >> 2);
            int col  = n_base + nj * 8 + (lane & 3) * 2;
            float si0 = sSinv[col];
            float si1 = sSinv[col + 1];
            __nv_bfloat162 h0 = __floats2bfloat162_rn(acc[mi][nj][0] * si0,
                                                      acc[mi][nj][1] * si1);
            __nv_bfloat162 h1 = __floats2bfloat162_rn(acc[mi][nj][2] * si0,
                                                      acc[mi][nj][3] * si1);
            *(__nv_bfloat162*)&g_a2h[b][t0 + row0][s0 + col]     = h0;
            *(__nv_bfloat162*)&g_a2h[b][t0 + row0 + 8][s0 + col] = h1;
        }
    }
}

// ---------------------------------------------------------------------------
// Kernel 4: softmax + scatter. 512 threads; each thread owns <=2 row elements
// kept in REGISTERS (no sexp smem). exp via deg-4 Taylor (|x| < ~0.02).
// ---------------------------------------------------------------------------
__device__ __forceinline__ float exp_poly(float x) {
    return 1.0f + x * (1.0f + x * (0.5f + x * (0.16666667f + x * 0.041666667f)));
}

__global__ __launch_bounds__(512) void k_out(const int* __restrict__ idx,
                                             float* __restrict__ out) {
    int t = blockIdx.x;
    int b = blockIdx.y;
    int n = t + 1;
    int tid = threadIdx.x;

    __shared__ float sacc[VV];            // 8 KB
    __shared__ int   sidx[TT];            // 4 KB
    __shared__ float sred[16];

    const __nv_bfloat16* row = &g_a2h[b][t][0];

    // stage idx row (first 256 threads), zero accumulator
    if (tid < 256) ((int4*)sidx)[tid] = ((const int4*)(idx + b * TT))[tid];
    ((float4*)sacc)[tid] = make_float4(0.f, 0.f, 0.f, 0.f);

    // exp into registers + sum
    int s0 = tid, s1 = tid + 512;
    float p0 = 0.0f, p1 = 0.0f;
    if (s0 < n) p0 = exp_poly(__bfloat162float(row[s0]));
    if (s1 < n) p1 = exp_poly(__bfloat162float(row[s1]));
    float sum = p0 + p1;
#pragma unroll
    for (int off = 16; off > 0; off >>= 1)
        sum += __shfl_xor_sync(0xffffffff, sum, off);
    if ((tid & 31) == 0) sred[tid >> 5] = sum;
    __syncthreads();
    if (tid < 16) {
        float v = sred[tid];
#pragma unroll
        for (int off = 8; off > 0; off >>= 1)
            v += __shfl_xor_sync(0xffff, v, off);
        if (tid == 0) sred[0] = v;
    }
    __syncthreads();
    float inv = 1.0f / sred[0];

    if (s0 < n) atomicAdd(&sacc[sidx[s0]], p0 * inv);
    if (s1 < n) atomicAdd(&sacc[sidx[s1]], p1 * inv);
    __syncthreads();

    // write output row (512 float4 = one iteration)
    float4* dst = (float4*)(out + ((size_t)(b * TT + t)) * VV);
    dst[tid] = ((const float4*)sacc)[tid];
}

// ---------------------------------------------------------------------------
extern "C" void kernel_launch(void* const* d_in, const int* in_sizes, int n_in,
                              void* d_out, int out_size) {
    const int*   idx = nullptr;
    const float* vw  = nullptr;
    const float* W   = nullptr;
    for (int i = 0; i < n_in; i++) {
        if (in_sizes[i] == BB * TT)       idx = (const int*)d_in[i];
        else if (in_sizes[i] == TT)       vw  = (const float*)d_in[i];
        else if (in_sizes[i] == VV * VV)  W   = (const float*)d_in[i];
    }
    float* out = (float*)d_out;

    k_prefix<<<1, TT>>>(vw);

    dim3 gGather(TT, BB);
    k_gather<<<gGather, 256>>>(idx, W);

    dim3 gGemm(36, BB);
    k_gemm<<<gGemm, 256>>>();

    dim3 gOut(TT, BB);
    k_out<<<gOut, 512>>>(idx, out);
}

// round 9
// speedup vs baseline: 1.3298x; 1.3298x over previous
#include <cuda_runtime.h>
#include <cuda_bf16.h>
#include <math.h>
#include <stdint.h>

#define BB 8
#define TT 1024
#define VV 2048

// Scratch (__device__ globals: allocation-free rule)
__device__ __nv_bfloat16 g_Ebf[TT];            // bf16-rounded exp(vw[d])
__device__ float         g_Sinv[TT];           // 1 / prefix_sum(round_bf16(exp(vw)))
__device__ __nv_bfloat16 g_M[BB][TT][TT];      // bf16(W[idx_t][idx_s'])   (16MB)
__device__ __nv_bfloat16 g_a2h[BB][TT][TT];    // pre-softmax scores, bf16 (16MB)

// ---------------------------------------------------------------------------
// Kernel 1: E, Sinv.  Round E to bf16 FIRST, then scan the rounded values so
// the layer-1 softmax weights used by the GEMM sum to ~1 exactly.
// ---------------------------------------------------------------------------
__global__ void k_prefix(const float* __restrict__ vw) {
    __shared__ float sc[TT];
    int i = threadIdx.x;                  // blockDim = 1024
    float e = expf(vw[i]);
    __nv_bfloat16 eb = __float2bfloat16(e);
    float er = __bfloat162float(eb);
    g_Ebf[i] = eb;
    sc[i] = er;
    __syncthreads();
    for (int off = 1; off < TT; off <<= 1) {
        float v = (i >= off) ? sc[i - off] : 0.0f;
        __syncthreads();
        sc[i] += v;
        __syncthreads();
    }
    g_Sinv[i] = 1.0f / sc[i];
}

// ---------------------------------------------------------------------------
// Kernel 2: gather M[b][t][s'] = bf16(W[idx[b,t]][idx[b,s']])
// ---------------------------------------------------------------------------
__global__ __launch_bounds__(256) void k_gather(const int* __restrict__ idx,
                                                const float* __restrict__ W) {
    int t = blockIdx.x;
    int b = blockIdx.y;
    __shared__ float row[VV];
    __shared__ int   sidx[TT];

    int wr = idx[b * TT + t];
    const float4* src = (const float4*)(W + (size_t)wr * VV);
    float4* rdst = (float4*)row;
    for (int i = threadIdx.x; i < VV / 4; i += 256) rdst[i] = src[i];
    const int4* isrc = (const int4*)(idx + b * TT);
    int4* idst = (int4*)sidx;
    for (int i = threadIdx.x; i < TT / 4; i += 256) idst[i] = isrc[i];
    __syncthreads();

    __nv_bfloat162* om = (__nv_bfloat162*)(&g_M[b][t][0]);
    for (int p = threadIdx.x; p < TT / 2; p += 256) {
        float v0 = row[sidx[2 * p + 0]];
        float v1 = row[sidx[2 * p + 1]];
        om[p] = __floats2bfloat162_rn(v0, v1);
    }
}

// ---------------------------------------------------------------------------
// Kernel 3: bf16 tensor-core GEMM, 2-stage cp.async pipeline (single plane).
//   a2[b][t][s] = Sinv[s] * sum_{k<=s} M[t,k] * E[s-k]   -> bf16
// ---------------------------------------------------------------------------
#define APITCH 24            // bf16 units per A row in smem (48B, conflict-free)

__device__ __forceinline__ uint32_t smem_u32(const void* p) {
    return (uint32_t)__cvta_generic_to_shared(p);
}
__device__ __forceinline__ void cp16(uint32_t dst, const void* src) {
    asm volatile("cp.async.ca.shared.global [%0], [%1], 16;\n" :: "r"(dst), "l"(src));
}

__global__ __launch_bounds__(256, 2) void k_gemm() {
    int b = blockIdx.y;
    int p = blockIdx.x;
    int ti = 0;
    while ((ti + 1) * (ti + 2) / 2 <= p) ti++;
    int si = p - ti * (ti + 1) / 2;
    int t0 = ti * 128;
    int s0 = si * 128;

    __shared__ __align__(16) __nv_bfloat16 As[2][128 * APITCH];   // [stage] 12 KB
    __shared__ __align__(16) unsigned char Bs[2][16 * 256];       // [stage] 8 KB swizzled
    __shared__ __nv_bfloat16 sE[TT];                              // 2 KB
    __shared__ float sSinv[128];

    int tid  = threadIdx.x;
    int wid  = tid >> 5;
    int lane = tid & 31;
    int m_base = (wid >> 1) * 32;
    int n_base = (wid & 1) * 64;

    {
        const uint2* esrc = (const uint2*)g_Ebf;
        uint2* edst = (uint2*)sE;
        for (int i = tid; i < TT / 4; i += 256) edst[i] = esrc[i];
        if (tid < 128) sSinv[tid] = g_Sinv[s0 + tid];
    }

    float acc[2][8][4];
#pragma unroll
    for (int mi = 0; mi < 2; mi++)
#pragma unroll
        for (int nj = 0; nj < 8; nj++)
#pragma unroll
            for (int r = 0; r < 4; r++) acc[mi][nj][r] = 0.0f;

    int a_row = tid >> 1;
    int a_vec = tid & 1;
    int b_k  = tid >> 4;
    int b_vn = tid & 15;
    int nsteps = (s0 + 128) >> 4;

    auto issueA = [&](int stage, int k0) {
        uint32_t d0 = smem_u32(&As[stage][a_row * APITCH + a_vec * 8]);
        cp16(d0, &g_M[b][t0 + a_row][k0 + a_vec * 8]);
        asm volatile("cp.async.commit_group;\n");
    };
    auto issueB = [&](int stage, int k0) {
        union { __nv_bfloat16 h[8]; uint4 u; } pk;
        int dbase = (s0 + b_vn * 8) - (k0 + b_k);
#pragma unroll
        for (int j = 0; j < 8; j++) {
            int d = dbase + j;
            pk.h[j] = (d >= 0) ? sE[d] : __float2bfloat16(0.0f);
        }
        int phys = b_k * 256 + ((b_vn ^ (b_k & 7)) * 16);
        *(uint4*)(Bs[stage] + phys) = pk.u;
    };

    __syncthreads();   // sE/sSinv ready (needed by issueB)
    issueA(0, 0);
    issueB(0, 0);

    for (int step = 0; step < nsteps; step++) {
        int stage = step & 1;
        asm volatile("cp.async.wait_group 0;\n");
        __syncthreads();

        if (step + 1 < nsteps) {
            issueA(stage ^ 1, (step + 1) * 16);
            issueB(stage ^ 1, (step + 1) * 16);
        }

        uint32_t bfr[8][2];
#pragma unroll
        for (int nj2 = 0; nj2 < 4; nj2++) {
            int nvec = (n_base >> 3) + nj2 * 2 + (lane >> 4);
            int krow = lane & 15;
            uint32_t addr = smem_u32(Bs[stage] + krow * 256 + ((nvec ^ (krow & 7)) * 16));
            uint32_t r0, r1, r2, r3;
            asm volatile("ldmatrix.sync.aligned.m8n8.x4.trans.shared.b16 {%0,%1,%2,%3}, [%4];"
                         : "=r"(r0), "=r"(r1), "=r"(r2), "=r"(r3)
                         : "r"(addr));
            bfr[nj2 * 2 + 0][0] = r0; bfr[nj2 * 2 + 0][1] = r1;
            bfr[nj2 * 2 + 1][0] = r2; bfr[nj2 * 2 + 1][1] = r3;
        }

        uint32_t afr[2][4];
#pragma unroll
        for (int mi = 0; mi < 2; mi++) {
            int row = m_base + mi * 16 + (lane & 15);
            uint32_t addr = smem_u32(&As[stage][row * APITCH + (lane >> 4) * 8]);
            asm volatile("ldmatrix.sync.aligned.m8n8.x4.shared.b16 {%0,%1,%2,%3}, [%4];"
                         : "=r"(afr[mi][0]), "=r"(afr[mi][1]),
                           "=r"(afr[mi][2]), "=r"(afr[mi][3])
                         : "r"(addr));
        }
#pragma unroll
        for (int mi = 0; mi < 2; mi++)
#pragma unroll
            for (int nj = 0; nj < 8; nj++) {
                asm volatile(
                    "mma.sync.aligned.m16n8k16.row.col.f32.bf16.bf16.f32 "
                    "{%0,%1,%2,%3}, {%4,%5,%6,%7}, {%8,%9}, {%0,%1,%2,%3};"
                    : "+f"(acc[mi][nj][0]), "+f"(acc[mi][nj][1]),
                      "+f"(acc[mi][nj][2]), "+f"(acc[mi][nj][3])
                    : "r"(afr[mi][0]), "r"(afr[mi][1]), "r"(afr[mi][2]), "r"(afr[mi][3]),
                      "r"(bfr[nj][0]), "r"(bfr[nj][1]));
            }
    }

    // ---- epilogue: scale by Sinv[s], store bf16 ----
    // m16n8k16 D-fragment: c0,c1 -> (row, col/col+1); c2,c3 -> (row+8, col/col+1)
#pragma unroll
    for (int mi = 0; mi < 2; mi++) {
#pragma unroll
        for (int nj = 0; nj < 8; nj++) {
            int row0 = m_base + mi * 16 + (lane >> 2);
            int col  = n_base + nj * 8 + (lane & 3) * 2;
            float si0 = sSinv[col];
            float si1 = sSinv[col + 1];
            __nv_bfloat162 h0 = __floats2bfloat162_rn(acc[mi][nj][0] * si0,
                                                      acc[mi][nj][1] * si1);
            __nv_bfloat162 h1 = __floats2bfloat162_rn(acc[mi][nj][2] * si0,
                                                      acc[mi][nj][3] * si1);
            *(__nv_bfloat162*)&g_a2h[b][t0 + row0][s0 + col]     = h0;
            *(__nv_bfloat162*)&g_a2h[b][t0 + row0 + 8][s0 + col] = h1;
        }
    }
}

// ---------------------------------------------------------------------------
// Kernel 4: softmax + scatter. 4 rows per block, four independent 128-thread
// groups synced via named barriers; idx row staged once per block.
// ---------------------------------------------------------------------------
__device__ __forceinline__ float exp_poly(float x) {
    return 1.0f + x * (1.0f + x * (0.5f + x * (0.16666667f + x * 0.041666667f)));
}
__device__ __forceinline__ void bar_g(int id) {
    asm volatile("bar.sync %0, 128;" :: "r"(id + 1) : "memory");
}

__global__ __launch_bounds__(512) void k_out(const int* __restrict__ idx,
                                             float* __restrict__ out) {
    int b  = blockIdx.y;
    int tb = blockIdx.x * 4;              // first of 4 rows for this block
    int tid = threadIdx.x;
    int g   = tid >> 7;                   // group 0..3
    int gt  = tid & 127;                  // thread within group
    int t   = tb + g;
    int n   = t + 1;

    __shared__ float sacc[4][VV];         // 32 KB
    __shared__ int   sidx[TT];            // 4 KB
    __shared__ float sred[4][4];

    // whole-block: stage idx row once
    if (tid < 256) ((int4*)sidx)[tid] = ((const int4*)(idx + b * TT))[tid];
    // each group zeroes its own accumulator (128 thr x 16 floats)
    {
        float4* z = (float4*)sacc[g];
#pragma unroll
        for (int j = 0; j < 4; j++) z[gt + j * 128] = make_float4(0.f, 0.f, 0.f, 0.f);
    }
    __syncthreads();                      // sidx visible to all groups

    const __nv_bfloat16* row = &g_a2h[b][t][0];

    // each thread owns 8 strided elements, kept in registers
    float pv[8];
    float sum = 0.0f;
#pragma unroll
    for (int j = 0; j < 8; j++) {
        int s = gt + j * 128;
        float e = 0.0f;
        if (s < n) e = exp_poly(__bfloat162float(row[s]));
        pv[j] = e;
        sum += e;
    }
#pragma unroll
    for (int off = 16; off > 0; off >>= 1)
        sum += __shfl_xor_sync(0xffffffff, sum, off);
    if ((gt & 31) == 0) sred[g][gt >> 5] = sum;
    bar_g(g);
    float inv = 1.0f / (sred[g][0] + sred[g][1] + sred[g][2] + sred[g][3]);

#pragma unroll
    for (int j = 0; j < 8; j++) {
        int s = gt + j * 128;
        if (s < n) atomicAdd(&sacc[g][sidx[s]], pv[j] * inv);
    }
    bar_g(g);

    // write output row: 2048 floats = 512 float4 per group (128 thr x 4)
    float4* dst = (float4*)(out + ((size_t)(b * TT + t)) * VV);
    const float4* src = (const float4*)sacc[g];
#pragma unroll
    for (int j = 0; j < 4; j++) dst[gt + j * 128] = src[gt + j * 128];
}

// ---------------------------------------------------------------------------
extern "C" void kernel_launch(void* const* d_in, const int* in_sizes, int n_in,
                              void* d_out, int out_size) {
    const int*   idx = nullptr;
    const float* vw  = nullptr;
    const float* W   = nullptr;
    for (int i = 0; i < n_in; i++) {
        if (in_sizes[i] == BB * TT)       idx = (const int*)d_in[i];
        else if (in_sizes[i] == TT)       vw  = (const float*)d_in[i];
        else if (in_sizes[i] == VV * VV)  W   = (const float*)d_in[i];
    }
    float* out = (float*)d_out;

    k_prefix<<<1, TT>>>(vw);

    dim3 gGather(TT, BB);
    k_gather<<<gGather, 256>>>(idx, W);

    dim3 gGemm(36, BB);
    k_gemm<<<gGemm, 256>>>();

    dim3 gOut(TT / 4, BB);
    k_out<<<gOut, 512>>>(idx, out);
}

// round 10
// speedup vs baseline: 1.5233x; 1.1455x over previous
#include <cuda_runtime.h>
#include <cuda_bf16.h>
#include <math.h>
#include <stdint.h>

#define BB 8
#define TT 1024
#define VV 2048

// Scratch (__device__ globals: allocation-free rule)
__device__ __nv_bfloat16 g_Ebf[TT];            // bf16-rounded exp(vw[d])
__device__ float         g_Sinv[TT];           // 1 / prefix_sum(round_bf16(exp(vw)))
__device__ __nv_bfloat16 g_M[BB][TT][TT];      // bf16(W[idx_t][idx_s'])   (16MB)
__device__ __nv_bfloat16 g_a2h[BB][TT][TT];    // pre-softmax scores, bf16 (16MB)

// ---------------------------------------------------------------------------
// Kernel 1: E, Sinv via shfl warp-scan (2 barriers total).
// ---------------------------------------------------------------------------
__global__ void k_prefix(const float* __restrict__ vw) {
    __shared__ float wsum[32];
    int i = threadIdx.x;                  // blockDim = 1024
    int lane = i & 31, wid = i >> 5;
    float e = expf(vw[i]);
    __nv_bfloat16 eb = __float2bfloat16(e);
    float x = __bfloat162float(eb);
    g_Ebf[i] = eb;
    // warp inclusive scan
#pragma unroll
    for (int off = 1; off < 32; off <<= 1) {
        float y = __shfl_up_sync(0xffffffff, x, off);
        if (lane >= off) x += y;
    }
    if (lane == 31) wsum[wid] = x;
    __syncthreads();
    if (wid == 0) {
        float v = wsum[lane];
#pragma unroll
        for (int off = 1; off < 32; off <<= 1) {
            float y = __shfl_up_sync(0xffffffff, v, off);
            if (lane >= off) v += y;
        }
        wsum[lane] = v;
    }
    __syncthreads();
    float base = (wid > 0) ? wsum[wid - 1] : 0.0f;
    g_Sinv[i] = 1.0f / (base + x);
}

// ---------------------------------------------------------------------------
// Kernel 2: gather M[b][t][s'] = bf16(W[idx[b,t]][idx[b,s']]).
// 4 rows per block: 4 groups x 128 threads, one __syncthreads.
// ---------------------------------------------------------------------------
__global__ __launch_bounds__(512) void k_gather(const int* __restrict__ idx,
                                                const float* __restrict__ W) {
    int b  = blockIdx.y;
    int g  = threadIdx.x >> 7;            // group 0..3
    int gt = threadIdx.x & 127;
    int t  = blockIdx.x * 4 + g;

    __shared__ float rows[4][VV];         // 32 KB
    __shared__ int   sidx[TT];            // 4 KB

    if (threadIdx.x < 256)
        ((int4*)sidx)[threadIdx.x] = ((const int4*)(idx + b * TT))[threadIdx.x];

    int wr = idx[b * TT + t];
    const float4* src = (const float4*)(W + (size_t)wr * VV);
    float4* rdst = (float4*)rows[g];
#pragma unroll
    for (int j = 0; j < 4; j++) rdst[gt + j * 128] = src[gt + j * 128];
    __syncthreads();

    __nv_bfloat162* om = (__nv_bfloat162*)(&g_M[b][t][0]);
    const float* row = rows[g];
#pragma unroll
    for (int j = 0; j < 4; j++) {
        int p = gt + j * 128;
        om[p] = __floats2bfloat162_rn(row[sidx[2 * p + 0]], row[sidx[2 * p + 1]]);
    }
}

// ---------------------------------------------------------------------------
// Kernel 3: bf16 tensor-core GEMM, TK=32, 2-stage cp.async pipeline,
// heavy-light balanced 1-D block mapping over (b, ti, si) triangular tiles.
//   a2[b][t][s] = Sinv[s] * sum_{k<=s} M[t,k] * E[s-k]   -> bf16
// ---------------------------------------------------------------------------
__device__ __forceinline__ uint32_t smem_u32(const void* p) {
    return (uint32_t)__cvta_generic_to_shared(p);
}
__device__ __forceinline__ void cp16(uint32_t dst, const void* src) {
    asm volatile("cp.async.ca.shared.global [%0], [%1], 16;\n" :: "r"(dst), "l"(src));
}

__global__ __launch_bounds__(256, 2) void k_gemm() {
    // ---- heavy-light interleaved mapping ----
    int r = blockIdx.x;                            // 0..287
    int k = (r < 144) ? (2 * r) : (2 * (287 - r) + 1);   // rank in desc-weight order
    int si, off;
    if      (k <   8) { si = 7; off = 0;   }
    else if (k <  24) { si = 6; off = 8;   }
    else if (k <  48) { si = 5; off = 24;  }
    else if (k <  80) { si = 4; off = 48;  }
    else if (k < 120) { si = 3; off = 80;  }
    else if (k < 168) { si = 2; off = 120; }
    else if (k < 224) { si = 1; off = 168; }
    else              { si = 0; off = 224; }
    int m  = k - off;
    int ti = si + (m >> 3);
    int b  = m & 7;
    int t0 = ti * 128;
    int s0 = si * 128;

    __shared__ __align__(16) unsigned char Ab[2][128 * 64];   // 16 KB, swizzled 64B rows
    __shared__ __align__(16) unsigned char Bb[2][32 * 256];   // 16 KB, swizzled
    __shared__ __nv_bfloat16 sE[TT];                          // 2 KB
    __shared__ float sSinv[128];

    int tid  = threadIdx.x;
    int wid  = tid >> 5;
    int lane = tid & 31;
    int m_base = (wid >> 1) * 32;
    int n_base = (wid & 1) * 64;

    {
        const uint2* esrc = (const uint2*)g_Ebf;
        uint2* edst = (uint2*)sE;
        for (int i = tid; i < TT / 4; i += 256) edst[i] = esrc[i];
        if (tid < 128) sSinv[tid] = g_Sinv[s0 + tid];
    }

    float acc[2][8][4];
#pragma unroll
    for (int mi = 0; mi < 2; mi++)
#pragma unroll
        for (int nj = 0; nj < 8; nj++)
#pragma unroll
            for (int q = 0; q < 4; q++) acc[mi][nj][q] = 0.0f;

    int a_row = tid >> 1;
    int a_v0  = (tid & 1) * 2;            // 2 of 4 16B-vecs per row
    int b_k   = tid >> 4;                 // B rows b_k and b_k+16
    int b_vn  = tid & 15;
    int nsteps = (s0 + 128) >> 5;         // TK=32

    auto issueA = [&](int stage, int k0) {
#pragma unroll
        for (int vv = 0; vv < 2; vv++) {
            int v = a_v0 + vv;
            uint32_t dst = smem_u32(Ab[stage] + a_row * 64 + ((v ^ (a_row & 3)) * 16));
            cp16(dst, &g_M[b][t0 + a_row][k0 + v * 8]);
        }
        asm volatile("cp.async.commit_group;\n");
    };
    auto issueB = [&](int stage, int k0) {
#pragma unroll
        for (int rr2 = 0; rr2 < 2; rr2++) {
            int rr = b_k + rr2 * 16;
            union { __nv_bfloat16 h[8]; uint4 u; } pk;
            int dbase = (s0 + b_vn * 8) - (k0 + rr);
#pragma unroll
            for (int j = 0; j < 8; j++) {
                int d = dbase + j;
                pk.h[j] = (d >= 0) ? sE[d] : __float2bfloat16(0.0f);
            }
            *(uint4*)(Bb[stage] + rr * 256 + ((b_vn ^ (rr & 7)) * 16)) = pk.u;
        }
    };

    __syncthreads();   // sE/sSinv ready
    issueA(0, 0);
    issueB(0, 0);

    for (int step = 0; step < nsteps; step++) {
        int stage = step & 1;
        asm volatile("cp.async.wait_group 0;\n");
        __syncthreads();

        if (step + 1 < nsteps) {
            issueA(stage ^ 1, (step + 1) * 32);
            issueB(stage ^ 1, (step + 1) * 32);
        }

#pragma unroll
        for (int kc = 0; kc < 32; kc += 16) {
            uint32_t afr[2][4];
#pragma unroll
            for (int mi = 0; mi < 2; mi++) {
                int row = m_base + mi * 16 + (lane & 15);
                int v   = (kc >> 3) + (lane >> 4);
                uint32_t addr = smem_u32(Ab[stage] + row * 64 + ((v ^ (row & 3)) * 16));
                asm volatile("ldmatrix.sync.aligned.m8n8.x4.shared.b16 {%0,%1,%2,%3}, [%4];"
                             : "=r"(afr[mi][0]), "=r"(afr[mi][1]),
                               "=r"(afr[mi][2]), "=r"(afr[mi][3])
                             : "r"(addr));
            }
            uint32_t bfr[8][2];
#pragma unroll
            for (int nj2 = 0; nj2 < 4; nj2++) {
                int nvec = (n_base >> 3) + nj2 * 2 + (lane >> 4);
                int krow = kc + (lane & 15);
                uint32_t addr = smem_u32(Bb[stage] + krow * 256 + ((nvec ^ (krow & 7)) * 16));
                uint32_t r0, r1, r2, r3;
                asm volatile("ldmatrix.sync.aligned.m8n8.x4.trans.shared.b16 {%0,%1,%2,%3}, [%4];"
                             : "=r"(r0), "=r"(r1), "=r"(r2), "=r"(r3)
                             : "r"(addr));
                bfr[nj2 * 2 + 0][0] = r0; bfr[nj2 * 2 + 0][1] = r1;
                bfr[nj2 * 2 + 1][0] = r2; bfr[nj2 * 2 + 1][1] = r3;
            }
#pragma unroll
            for (int mi = 0; mi < 2; mi++)
#pragma unroll
                for (int nj = 0; nj < 8; nj++) {
                    asm volatile(
                        "mma.sync.aligned.m16n8k16.row.col.f32.bf16.bf16.f32 "
                        "{%0,%1,%2,%3}, {%4,%5,%6,%7}, {%8,%9}, {%0,%1,%2,%3};"
                        : "+f"(acc[mi][nj][0]), "+f"(acc[mi][nj][1]),
                          "+f"(acc[mi][nj][2]), "+f"(acc[mi][nj][3])
                        : "r"(afr[mi][0]), "r"(afr[mi][1]), "r"(afr[mi][2]), "r"(afr[mi][3]),
                          "r"(bfr[nj][0]), "r"(bfr[nj][1]));
                }
        }
    }

    // ---- epilogue: scale by Sinv[s], store bf16 ----
    // m16n8k16 D-fragment: c0,c1 -> (row, col/col+1); c2,c3 -> (row+8, col/col+1)
#pragma unroll
    for (int mi = 0; mi < 2; mi++) {
#pragma unroll
        for (int nj = 0; nj < 8; nj++) {
            int row0 = m_base + mi * 16 + (lane >> 2);
            int col  = n_base + nj * 8 + (lane & 3) * 2;
            float si0 = sSinv[col];
            float si1 = sSinv[col + 1];
            __nv_bfloat162 h0 = __floats2bfloat162_rn(acc[mi][nj][0] * si0,
                                                      acc[mi][nj][1] * si1);
            __nv_bfloat162 h1 = __floats2bfloat162_rn(acc[mi][nj][2] * si0,
                                                      acc[mi][nj][3] * si1);
            *(__nv_bfloat162*)&g_a2h[b][t0 + row0][s0 + col]     = h0;
            *(__nv_bfloat162*)&g_a2h[b][t0 + row0 + 8][s0 + col] = h1;
        }
    }
}

// ---------------------------------------------------------------------------
// Kernel 4: softmax + scatter. 4 rows per block, four independent 128-thread
// groups synced via named barriers; idx row staged once per block.
// ---------------------------------------------------------------------------
__device__ __forceinline__ float exp_poly(float x) {
    return 1.0f + x * (1.0f + x * (0.5f + x * (0.16666667f + x * 0.041666667f)));
}
__device__ __forceinline__ void bar_g(int id) {
    asm volatile("bar.sync %0, 128;" :: "r"(id + 1) : "memory");
}

__global__ __launch_bounds__(512) void k_out(const int* __restrict__ idx,
                                             float* __restrict__ out) {
    int b  = blockIdx.y;
    int tb = blockIdx.x * 4;
    int tid = threadIdx.x;
    int g   = tid >> 7;
    int gt  = tid & 127;
    int t   = tb + g;
    int n   = t + 1;

    __shared__ float sacc[4][VV];         // 32 KB
    __shared__ int   sidx[TT];            // 4 KB
    __shared__ float sred[4][4];

    if (tid < 256) ((int4*)sidx)[tid] = ((const int4*)(idx + b * TT))[tid];
    {
        float4* z = (float4*)sacc[g];
#pragma unroll
        for (int j = 0; j < 4; j++) z[gt + j * 128] = make_float4(0.f, 0.f, 0.f, 0.f);
    }
    __syncthreads();

    const __nv_bfloat16* row = &g_a2h[b][t][0];

    float pv[8];
    float sum = 0.0f;
#pragma unroll
    for (int j = 0; j < 8; j++) {
        int s = gt + j * 128;
        float e = 0.0f;
        if (s < n) e = exp_poly(__bfloat162float(row[s]));
        pv[j] = e;
        sum += e;
    }
#pragma unroll
    for (int off = 16; off > 0; off >>= 1)
        sum += __shfl_xor_sync(0xffffffff, sum, off);
    if ((gt & 31) == 0) sred[g][gt >> 5] = sum;
    bar_g(g);
    float inv = 1.0f / (sred[g][0] + sred[g][1] + sred[g][2] + sred[g][3]);

#pragma unroll
    for (int j = 0; j < 8; j++) {
        int s = gt + j * 128;
        if (s < n) atomicAdd(&sacc[g][sidx[s]], pv[j] * inv);
    }
    bar_g(g);

    float4* dst = (float4*)(out + ((size_t)(b * TT + t)) * VV);
    const float4* src = (const float4*)sacc[g];
#pragma unroll
    for (int j = 0; j < 4; j++) dst[gt + j * 128] = src[gt + j * 128];
}

// ---------------------------------------------------------------------------
extern "C" void kernel_launch(void* const* d_in, const int* in_sizes, int n_in,
                              void* d_out, int out_size) {
    const int*   idx = nullptr;
    const float* vw  = nullptr;
    const float* W   = nullptr;
    for (int i = 0; i < n_in; i++) {
        if (in_sizes[i] == BB * TT)       idx = (const int*)d_in[i];
        else if (in_sizes[i] == TT)       vw  = (const float*)d_in[i];
        else if (in_sizes[i] == VV * VV)  W   = (const float*)d_in[i];
    }
    float* out = (float*)d_out;

    k_prefix<<<1, TT>>>(vw);

    dim3 gGather(TT / 4, BB);
    k_gather<<<gGather, 512>>>(idx, W);

    k_gemm<<<288, 256>>>();

    dim3 gOut(TT / 4, BB);
    k_out<<<gOut, 512>>>(idx, out);
}